// round 13
// baseline (speedup 1.0000x reference)
#include <cuda_runtime.h>
#include <cuda_bf16.h>
#include <math.h>

#define N_NODES 50000
#define N_EDGES 800000
#define D_IN 192
#define D_OUT 64
#define CAP 96          // bucket capacity per node (true max deg ~45)

// ---------------- scratch (zero-initialized at module load) ----------------
__device__ float g_u[D_IN];                            // W^T w_att
__device__ int   g_cnt[N_NODES];                       // zeroed by invariant
__device__ int   g_bkt[(size_t)N_NODES * CAP];         // edge ids
__device__ float g_xagg[(size_t)N_NODES * D_IN];       // 38.4 MB

__device__ __forceinline__ float mish(float x) {
    float sp = fmaxf(x, 0.0f) + log1pf(expf(-fabsf(x)));
    return x * tanhf(sp);
}

// ---------------- kernel 1: bucket fill (dst -> edge list) ------------------
__global__ void histfill_kernel(const int* __restrict__ idx32, int n_edges) {
    __shared__ int s_is64;
    if (threadIdx.x == 0) {
        bool is64 = true;
        for (int j = 1; j < 64; j += 2)
            if (idx32[j] != 0) { is64 = false; break; }
        s_is64 = is64 ? 1 : 0;
    }
    __syncthreads();
    int e = blockIdx.x * blockDim.x + threadIdx.x;
    if (e < n_edges) {
        int d = idx32[s_is64 ? (2 * e) : e];
        int pos = atomicAdd(&g_cnt[d], 1);
        if (pos < CAP)
            g_bkt[(size_t)d * CAP + pos] = e;
    }
}

// ---------------- kernel 2: u = W^T w_att ----------------------------------
__global__ void u_kernel(const float* __restrict__ W,
                         const float* __restrict__ watt) {
    int k = threadIdx.x;
    if (k < D_IN) {
        float s = 0.0f;
        for (int c = 0; c < D_OUT; c++)
            s = fmaf(W[c * D_IN + k], watt[c], s);
        g_u[k] = s;
    }
}

// ---------------- kernel 3: SINGLE-PASS fused logits+softmax+aggregation ---
// Measured ~DRAM-bound (X read once). Unchanged.
__global__ __launch_bounds__(256) void aggregate_kernel(
    const float* __restrict__ X, int n_nodes)
{
    const int node = (blockIdx.x * blockDim.x + threadIdx.x) >> 5;
    if (node >= n_nodes) return;
    const int lane = threadIdx.x & 31;
    const int deg = min(g_cnt[node], CAP);

    const float2* u2 = (const float2*)g_u;
    const float2 ua = u2[lane];
    const float2 ub = u2[32 + lane];
    const float2 uc = u2[64 + lane];

    float2 a0 = make_float2(0.f, 0.f);
    float2 a1 = make_float2(0.f, 0.f);
    float2 a2 = make_float2(0.f, 0.f);
    float dsum = 0.0f;
    const float2* X2 = (const float2*)X;
    const int* bkt = g_bkt + (size_t)node * CAP;

    int base = 0;
    for (; base + 4 <= deg; base += 4) {
        int e0 = bkt[base], e1 = bkt[base + 1];
        int e2 = bkt[base + 2], e3 = bkt[base + 3];
        const float2* r0 = X2 + (size_t)e0 * 96;
        const float2* r1 = X2 + (size_t)e1 * 96;
        const float2* r2 = X2 + (size_t)e2 * 96;
        const float2* r3 = X2 + (size_t)e3 * 96;
        float2 v00 = r0[lane], v01 = r0[32 + lane], v02 = r0[64 + lane];
        float2 v10 = r1[lane], v11 = r1[32 + lane], v12 = r1[64 + lane];
        float2 v20 = r2[lane], v21 = r2[32 + lane], v22 = r2[64 + lane];
        float2 v30 = r3[lane], v31 = r3[32 + lane], v32 = r3[64 + lane];

        float d0 = fmaf(v00.x, ua.x, fmaf(v00.y, ua.y,
                   fmaf(v01.x, ub.x, fmaf(v01.y, ub.y,
                   fmaf(v02.x, uc.x, v02.y * uc.y)))));
        float d1 = fmaf(v10.x, ua.x, fmaf(v10.y, ua.y,
                   fmaf(v11.x, ub.x, fmaf(v11.y, ub.y,
                   fmaf(v12.x, uc.x, v12.y * uc.y)))));
        float d2 = fmaf(v20.x, ua.x, fmaf(v20.y, ua.y,
                   fmaf(v21.x, ub.x, fmaf(v21.y, ub.y,
                   fmaf(v22.x, uc.x, v22.y * uc.y)))));
        float d3 = fmaf(v30.x, ua.x, fmaf(v30.y, ua.y,
                   fmaf(v31.x, ub.x, fmaf(v31.y, ub.y,
                   fmaf(v32.x, uc.x, v32.y * uc.y)))));
#pragma unroll
        for (int m = 16; m >= 1; m >>= 1) {
            d0 += __shfl_xor_sync(0xffffffffu, d0, m);
            d1 += __shfl_xor_sync(0xffffffffu, d1, m);
            d2 += __shfl_xor_sync(0xffffffffu, d2, m);
            d3 += __shfl_xor_sync(0xffffffffu, d3, m);
        }
        float w0 = expf(mish(d0));
        float w1 = expf(mish(d1));
        float w2 = expf(mish(d2));
        float w3 = expf(mish(d3));
        dsum += (w0 + w1) + (w2 + w3);
        a0.x = fmaf(v00.x, w0, a0.x); a0.y = fmaf(v00.y, w0, a0.y);
        a1.x = fmaf(v01.x, w0, a1.x); a1.y = fmaf(v01.y, w0, a1.y);
        a2.x = fmaf(v02.x, w0, a2.x); a2.y = fmaf(v02.y, w0, a2.y);
        a0.x = fmaf(v10.x, w1, a0.x); a0.y = fmaf(v10.y, w1, a0.y);
        a1.x = fmaf(v11.x, w1, a1.x); a1.y = fmaf(v11.y, w1, a1.y);
        a2.x = fmaf(v12.x, w1, a2.x); a2.y = fmaf(v12.y, w1, a2.y);
        a0.x = fmaf(v20.x, w2, a0.x); a0.y = fmaf(v20.y, w2, a0.y);
        a1.x = fmaf(v21.x, w2, a1.x); a1.y = fmaf(v21.y, w2, a1.y);
        a2.x = fmaf(v22.x, w2, a2.x); a2.y = fmaf(v22.y, w2, a2.y);
        a0.x = fmaf(v30.x, w3, a0.x); a0.y = fmaf(v30.y, w3, a0.y);
        a1.x = fmaf(v31.x, w3, a1.x); a1.y = fmaf(v31.y, w3, a1.y);
        a2.x = fmaf(v32.x, w3, a2.x); a2.y = fmaf(v32.y, w3, a2.y);
    }
    for (; base < deg; base++) {
        int e = bkt[base];
        const float2* r = X2 + (size_t)e * 96;
        float2 v0 = r[lane], v1 = r[32 + lane], v2 = r[64 + lane];
        float d = fmaf(v0.x, ua.x, fmaf(v0.y, ua.y,
                  fmaf(v1.x, ub.x, fmaf(v1.y, ub.y,
                  fmaf(v2.x, uc.x, v2.y * uc.y)))));
#pragma unroll
        for (int m = 16; m >= 1; m >>= 1)
            d += __shfl_xor_sync(0xffffffffu, d, m);
        float w = expf(mish(d));
        dsum += w;
        a0.x = fmaf(v0.x, w, a0.x); a0.y = fmaf(v0.y, w, a0.y);
        a1.x = fmaf(v1.x, w, a1.x); a1.y = fmaf(v1.y, w, a1.y);
        a2.x = fmaf(v2.x, w, a2.x); a2.y = fmaf(v2.y, w, a2.y);
    }

    const float inv = (deg > 0) ? (1.0f / dsum) : 0.0f;
    a0.x *= inv; a0.y *= inv;
    a1.x *= inv; a1.y *= inv;
    a2.x *= inv; a2.y *= inv;
    float2* dst = (float2*)&g_xagg[(size_t)node * D_IN];
    dst[lane] = a0;
    dst[32 + lane] = a1;
    dst[64 + lane] = a2;

    // restore zero-invariant for next call
    if (lane == 0) g_cnt[node] = 0;
}

// ---------------- kernel 4 (PROFILED): out = xagg @ W^T, v4 ----------------
// 64-node x 64-col tile, 512 threads (thread = 2 nodes x 4 cols).
// Same smem (99KB) but 16 warps/block, 2 blocks/SM -> 32 warps/SM for
// latency hiding (v3 had 16).
#define XSP 196
__global__ __launch_bounds__(512) void out_gemm_kernel(
    const float* __restrict__ W, float* __restrict__ out, int n_nodes)
{
    extern __shared__ float smem[];
    float* wsm = smem;              // [192][64]  wsm[k*64+c]
    float* xs = smem + 192 * 64;    // [64][XSP]

    const int tid = threadIdx.x;
    for (int l = tid; l < 192 * 64; l += 512) {
        int c = l / 192, k = l % 192;
        wsm[k * 64 + c] = W[l];
    }
    const int n0 = blockIdx.x * 64;
    for (int l = tid; l < 64 * 48; l += 512) {
        int n = l / 48, k4 = l % 48;
        float4 v = (n0 + n < n_nodes)
            ? *(const float4*)&g_xagg[(size_t)(n0 + n) * 192 + k4 * 4]
            : make_float4(0.f, 0.f, 0.f, 0.f);
        *(float4*)&xs[n * XSP + k4 * 4] = v;
    }
    __syncthreads();

    const int tx = tid & 15;        // col group: cols tx*4 .. +3
    const int ty = tid >> 4;        // node group 0..31: nodes ty*2, ty*2+1
    float acc[2][4];
#pragma unroll
    for (int i = 0; i < 2; i++)
#pragma unroll
        for (int j = 0; j < 4; j++) acc[i][j] = 0.0f;

#pragma unroll 4
    for (int k4 = 0; k4 < 48; k4++) {
        float4 xv[2];
#pragma unroll
        for (int i = 0; i < 2; i++)
            xv[i] = *(const float4*)&xs[(ty * 2 + i) * XSP + k4 * 4];
        float4 wv[4];
#pragma unroll
        for (int kk = 0; kk < 4; kk++)
            wv[kk] = *(const float4*)&wsm[(k4 * 4 + kk) * 64 + tx * 4];
#pragma unroll
        for (int kk = 0; kk < 4; kk++) {
#pragma unroll
            for (int i = 0; i < 2; i++) {
                float xk = (&xv[i].x)[kk];
                acc[i][0] = fmaf(xk, wv[kk].x, acc[i][0]);
                acc[i][1] = fmaf(xk, wv[kk].y, acc[i][1]);
                acc[i][2] = fmaf(xk, wv[kk].z, acc[i][2]);
                acc[i][3] = fmaf(xk, wv[kk].w, acc[i][3]);
            }
        }
    }
#pragma unroll
    for (int i = 0; i < 2; i++) {
        int n = n0 + ty * 2 + i;
        if (n < n_nodes)
            *(float4*)&out[(size_t)n * 64 + tx * 4] =
                make_float4(acc[i][0], acc[i][1], acc[i][2], acc[i][3]);
    }
}

// ---------------- launch -----------------------------------------------------
extern "C" void kernel_launch(void* const* d_in, const int* in_sizes, int n_in,
                              void* d_out, int out_size) {
    const float* X = (const float*)d_in[0];
    const int* idx32 = (const int*)d_in[1];
    const float* W = (const float*)d_in[2];
    const float* watt = (const float*)d_in[3];
    float* out = (float*)d_out;

    const int n_edges = in_sizes[0] / D_IN;   // 800000
    const int n_nodes = out_size / D_OUT;     // 50000

    const int outg_smem = (192 * 64 + 64 * XSP) * (int)sizeof(float);  // 99328
    cudaFuncSetAttribute(out_gemm_kernel,
                         cudaFuncAttributeMaxDynamicSharedMemorySize, outg_smem);

    histfill_kernel<<<(n_edges + 255) / 256, 256>>>(idx32, n_edges);    // 1
    u_kernel<<<1, 192>>>(W, watt);                                      // 2
    aggregate_kernel<<<(n_nodes * 32 + 255) / 256, 256>>>(X, n_nodes);  // 3
    out_gemm_kernel<<<(n_nodes + 63) / 64, 512, outg_smem>>>(W, out, n_nodes); // 4 (profiled)
}

// round 14
// speedup vs baseline: 1.1504x; 1.1504x over previous
#include <cuda_runtime.h>
#include <cuda_bf16.h>
#include <math.h>

#define N_NODES 50000
#define N_EDGES 800000
#define D_IN 192
#define D_OUT 64
#define CAP 96          // bucket capacity per node (true max deg ~45)

// ---------------- scratch (zero-initialized at module load) ----------------
__device__ float g_u[D_IN];                            // W^T w_att
__device__ float g_wt[D_IN * D_OUT];                   // W transposed: [k][c]
__device__ int   g_cnt[N_NODES];                       // zeroed by invariant
__device__ int   g_bkt[(size_t)N_NODES * CAP];         // edge ids
__device__ float g_xagg[(size_t)N_NODES * D_IN];       // 38.4 MB

__device__ __forceinline__ float mish(float x) {
    float sp = fmaxf(x, 0.0f) + log1pf(expf(-fabsf(x)));
    return x * tanhf(sp);
}

// ---------------- kernel 1: bucket fill (dst -> edge list) ------------------
__global__ void histfill_kernel(const int* __restrict__ idx32, int n_edges) {
    __shared__ int s_is64;
    if (threadIdx.x == 0) {
        bool is64 = true;
        for (int j = 1; j < 64; j += 2)
            if (idx32[j] != 0) { is64 = false; break; }
        s_is64 = is64 ? 1 : 0;
    }
    __syncthreads();
    int e = blockIdx.x * blockDim.x + threadIdx.x;
    if (e < n_edges) {
        int d = idx32[s_is64 ? (2 * e) : e];
        int pos = atomicAdd(&g_cnt[d], 1);
        if (pos < CAP)
            g_bkt[(size_t)d * CAP + pos] = e;
    }
}

// ---------------- kernel 2: u = W^T w_att  AND  g_wt = W^T (global) --------
// Block 0: compute u. Blocks 1..48: transpose W into g_wt[k*64+c]
// (coalesced writes; the strided reads are tiny and L2-hot).
__global__ void u_kernel(const float* __restrict__ W,
                         const float* __restrict__ watt) {
    if (blockIdx.x == 0) {
        int k = threadIdx.x;
        if (k < D_IN) {
            float s = 0.0f;
            for (int c = 0; c < D_OUT; c++)
                s = fmaf(W[c * D_IN + k], watt[c], s);
            g_u[k] = s;
        }
    } else {
        int idx = (blockIdx.x - 1) * 256 + threadIdx.x;   // 0..12287
        int c = idx & 63;
        int k = idx >> 6;
        g_wt[k * 64 + c] = W[c * 192 + k];
    }
}

// ---------------- kernel 3: SINGLE-PASS fused logits+softmax+aggregation ---
// Measured ~DRAM-bound (X read once). Unchanged.
__global__ __launch_bounds__(256) void aggregate_kernel(
    const float* __restrict__ X, int n_nodes)
{
    const int node = (blockIdx.x * blockDim.x + threadIdx.x) >> 5;
    if (node >= n_nodes) return;
    const int lane = threadIdx.x & 31;
    const int deg = min(g_cnt[node], CAP);

    const float2* u2 = (const float2*)g_u;
    const float2 ua = u2[lane];
    const float2 ub = u2[32 + lane];
    const float2 uc = u2[64 + lane];

    float2 a0 = make_float2(0.f, 0.f);
    float2 a1 = make_float2(0.f, 0.f);
    float2 a2 = make_float2(0.f, 0.f);
    float dsum = 0.0f;
    const float2* X2 = (const float2*)X;
    const int* bkt = g_bkt + (size_t)node * CAP;

    int base = 0;
    for (; base + 4 <= deg; base += 4) {
        int e0 = bkt[base], e1 = bkt[base + 1];
        int e2 = bkt[base + 2], e3 = bkt[base + 3];
        const float2* r0 = X2 + (size_t)e0 * 96;
        const float2* r1 = X2 + (size_t)e1 * 96;
        const float2* r2 = X2 + (size_t)e2 * 96;
        const float2* r3 = X2 + (size_t)e3 * 96;
        float2 v00 = r0[lane], v01 = r0[32 + lane], v02 = r0[64 + lane];
        float2 v10 = r1[lane], v11 = r1[32 + lane], v12 = r1[64 + lane];
        float2 v20 = r2[lane], v21 = r2[32 + lane], v22 = r2[64 + lane];
        float2 v30 = r3[lane], v31 = r3[32 + lane], v32 = r3[64 + lane];

        float d0 = fmaf(v00.x, ua.x, fmaf(v00.y, ua.y,
                   fmaf(v01.x, ub.x, fmaf(v01.y, ub.y,
                   fmaf(v02.x, uc.x, v02.y * uc.y)))));
        float d1 = fmaf(v10.x, ua.x, fmaf(v10.y, ua.y,
                   fmaf(v11.x, ub.x, fmaf(v11.y, ub.y,
                   fmaf(v12.x, uc.x, v12.y * uc.y)))));
        float d2 = fmaf(v20.x, ua.x, fmaf(v20.y, ua.y,
                   fmaf(v21.x, ub.x, fmaf(v21.y, ub.y,
                   fmaf(v22.x, uc.x, v22.y * uc.y)))));
        float d3 = fmaf(v30.x, ua.x, fmaf(v30.y, ua.y,
                   fmaf(v31.x, ub.x, fmaf(v31.y, ub.y,
                   fmaf(v32.x, uc.x, v32.y * uc.y)))));
#pragma unroll
        for (int m = 16; m >= 1; m >>= 1) {
            d0 += __shfl_xor_sync(0xffffffffu, d0, m);
            d1 += __shfl_xor_sync(0xffffffffu, d1, m);
            d2 += __shfl_xor_sync(0xffffffffu, d2, m);
            d3 += __shfl_xor_sync(0xffffffffu, d3, m);
        }
        float w0 = expf(mish(d0));
        float w1 = expf(mish(d1));
        float w2 = expf(mish(d2));
        float w3 = expf(mish(d3));
        dsum += (w0 + w1) + (w2 + w3);
        a0.x = fmaf(v00.x, w0, a0.x); a0.y = fmaf(v00.y, w0, a0.y);
        a1.x = fmaf(v01.x, w0, a1.x); a1.y = fmaf(v01.y, w0, a1.y);
        a2.x = fmaf(v02.x, w0, a2.x); a2.y = fmaf(v02.y, w0, a2.y);
        a0.x = fmaf(v10.x, w1, a0.x); a0.y = fmaf(v10.y, w1, a0.y);
        a1.x = fmaf(v11.x, w1, a1.x); a1.y = fmaf(v11.y, w1, a1.y);
        a2.x = fmaf(v12.x, w1, a2.x); a2.y = fmaf(v12.y, w1, a2.y);
        a0.x = fmaf(v20.x, w2, a0.x); a0.y = fmaf(v20.y, w2, a0.y);
        a1.x = fmaf(v21.x, w2, a1.x); a1.y = fmaf(v21.y, w2, a1.y);
        a2.x = fmaf(v22.x, w2, a2.x); a2.y = fmaf(v22.y, w2, a2.y);
        a0.x = fmaf(v30.x, w3, a0.x); a0.y = fmaf(v30.y, w3, a0.y);
        a1.x = fmaf(v31.x, w3, a1.x); a1.y = fmaf(v31.y, w3, a1.y);
        a2.x = fmaf(v32.x, w3, a2.x); a2.y = fmaf(v32.y, w3, a2.y);
    }
    for (; base < deg; base++) {
        int e = bkt[base];
        const float2* r = X2 + (size_t)e * 96;
        float2 v0 = r[lane], v1 = r[32 + lane], v2 = r[64 + lane];
        float d = fmaf(v0.x, ua.x, fmaf(v0.y, ua.y,
                  fmaf(v1.x, ub.x, fmaf(v1.y, ub.y,
                  fmaf(v2.x, uc.x, v2.y * uc.y)))));
#pragma unroll
        for (int m = 16; m >= 1; m >>= 1)
            d += __shfl_xor_sync(0xffffffffu, d, m);
        float w = expf(mish(d));
        dsum += w;
        a0.x = fmaf(v0.x, w, a0.x); a0.y = fmaf(v0.y, w, a0.y);
        a1.x = fmaf(v1.x, w, a1.x); a1.y = fmaf(v1.y, w, a1.y);
        a2.x = fmaf(v2.x, w, a2.x); a2.y = fmaf(v2.y, w, a2.y);
    }

    const float inv = (deg > 0) ? (1.0f / dsum) : 0.0f;
    a0.x *= inv; a0.y *= inv;
    a1.x *= inv; a1.y *= inv;
    a2.x *= inv; a2.y *= inv;
    float2* dst = (float2*)&g_xagg[(size_t)node * D_IN];
    dst[lane] = a0;
    dst[32 + lane] = a1;
    dst[64 + lane] = a2;

    // restore zero-invariant for next call
    if (lane == 0) g_cnt[node] = 0;
}

// ---------------- kernel 4 (PROFILED): out = xagg @ W^T, v6 ----------------
// v3 main loop (64x64 tile, 256 threads, 4 nodes x 4 cols) + CONFLICT-FREE
// W fill: g_wt is already [k][c], so the fill is a coalesced float4 copy
// (the old in-kernel transpose store was a 32-way STS bank conflict).
#define XSP 196
__global__ __launch_bounds__(256) void out_gemm_kernel(
    float* __restrict__ out, int n_nodes)
{
    extern __shared__ float smem[];
    float* wsm = smem;              // [192][64]  wsm[k*64+c]
    float* xs = smem + 192 * 64;    // [64][XSP]

    const int tid = threadIdx.x;
    // coalesced, conflict-free W fill (12288 floats = 3072 float4)
    const float4* wt4 = (const float4*)g_wt;
    float4* wsm4 = (float4*)wsm;
    for (int l = tid; l < 3072; l += 256)
        wsm4[l] = wt4[l];

    const int n0 = blockIdx.x * 64;
    for (int l = tid; l < 64 * 48; l += 256) {
        int n = l / 48, k4 = l % 48;
        float4 v = (n0 + n < n_nodes)
            ? *(const float4*)&g_xagg[(size_t)(n0 + n) * 192 + k4 * 4]
            : make_float4(0.f, 0.f, 0.f, 0.f);
        *(float4*)&xs[n * XSP + k4 * 4] = v;
    }
    __syncthreads();

    const int tx = tid & 15;        // col group: cols tx*4 .. +3
    const int ty = tid >> 4;        // node group: nodes ty*4 .. +3
    float acc[4][4];
#pragma unroll
    for (int i = 0; i < 4; i++)
#pragma unroll
        for (int j = 0; j < 4; j++) acc[i][j] = 0.0f;

#pragma unroll 2
    for (int k4 = 0; k4 < 48; k4++) {
        float4 xv[4];
#pragma unroll
        for (int i = 0; i < 4; i++)
            xv[i] = *(const float4*)&xs[(ty * 4 + i) * XSP + k4 * 4];
        float4 wv[4];
#pragma unroll
        for (int kk = 0; kk < 4; kk++)
            wv[kk] = *(const float4*)&wsm[(k4 * 4 + kk) * 64 + tx * 4];
#pragma unroll
        for (int kk = 0; kk < 4; kk++) {
#pragma unroll
            for (int i = 0; i < 4; i++) {
                float xk = (&xv[i].x)[kk];
                acc[i][0] = fmaf(xk, wv[kk].x, acc[i][0]);
                acc[i][1] = fmaf(xk, wv[kk].y, acc[i][1]);
                acc[i][2] = fmaf(xk, wv[kk].z, acc[i][2]);
                acc[i][3] = fmaf(xk, wv[kk].w, acc[i][3]);
            }
        }
    }
#pragma unroll
    for (int i = 0; i < 4; i++) {
        int n = n0 + ty * 4 + i;
        if (n < n_nodes)
            *(float4*)&out[(size_t)n * 64 + tx * 4] =
                make_float4(acc[i][0], acc[i][1], acc[i][2], acc[i][3]);
    }
}

// ---------------- launch -----------------------------------------------------
extern "C" void kernel_launch(void* const* d_in, const int* in_sizes, int n_in,
                              void* d_out, int out_size) {
    const float* X = (const float*)d_in[0];
    const int* idx32 = (const int*)d_in[1];
    const float* W = (const float*)d_in[2];
    const float* watt = (const float*)d_in[3];
    float* out = (float*)d_out;

    const int n_edges = in_sizes[0] / D_IN;   // 800000
    const int n_nodes = out_size / D_OUT;     // 50000

    const int outg_smem = (192 * 64 + 64 * XSP) * (int)sizeof(float);  // 99328
    cudaFuncSetAttribute(out_gemm_kernel,
                         cudaFuncAttributeMaxDynamicSharedMemorySize, outg_smem);

    histfill_kernel<<<(n_edges + 255) / 256, 256>>>(idx32, n_edges);    // 1
    u_kernel<<<49, 256>>>(W, watt);                                     // 2
    aggregate_kernel<<<(n_nodes * 32 + 255) / 256, 256>>>(X, n_nodes);  // 3
    out_gemm_kernel<<<(n_nodes + 63) / 64, 256, outg_smem>>>(out, n_nodes); // 4 (profiled)
}

// round 16
// speedup vs baseline: 1.1977x; 1.0411x over previous
#include <cuda_runtime.h>
#include <cuda_bf16.h>
#include <math.h>

#define N_NODES 50000
#define N_EDGES 800000
#define D_IN 192
#define D_OUT 64
#define CAP 96          // bucket capacity per node (true max deg ~45)

// ---------------- scratch (zero-initialized at module load) ----------------
__device__ float g_u[D_IN];                            // W^T w_att
__device__ float g_wt[D_IN * D_OUT];                   // W transposed: [k][c]
__device__ int   g_cnt[N_NODES];                       // zeroed by invariant
__device__ int   g_bkt[(size_t)N_NODES * CAP];         // edge ids
__device__ float g_xagg[(size_t)N_NODES * D_IN];       // 38.4 MB

__device__ __forceinline__ float mish(float x) {
    float sp = fmaxf(x, 0.0f) + log1pf(expf(-fabsf(x)));
    return x * tanhf(sp);
}

// ---------------- kernel 1: bucket fill + u + W^T (fused prep) -------------
// Blocks [0, EB): edge bucket fill. Block EB: u = W^T w_att.
// Blocks (EB, EB+48]: transpose W into g_wt (coalesced writes).
#define EB 3125
__global__ void histfill_kernel(const int* __restrict__ idx32,
                                const float* __restrict__ W,
                                const float* __restrict__ watt,
                                int n_edges) {
    if (blockIdx.x < EB) {
        __shared__ int s_is64;
        if (threadIdx.x == 0) {
            bool is64 = true;
            for (int j = 1; j < 64; j += 2)
                if (idx32[j] != 0) { is64 = false; break; }
            s_is64 = is64 ? 1 : 0;
        }
        __syncthreads();
        int e = blockIdx.x * blockDim.x + threadIdx.x;
        if (e < n_edges) {
            int d = idx32[s_is64 ? (2 * e) : e];
            int pos = atomicAdd(&g_cnt[d], 1);
            if (pos < CAP)
                g_bkt[(size_t)d * CAP + pos] = e;
        }
    } else if (blockIdx.x == EB) {
        int k = threadIdx.x;
        if (k < D_IN) {
            float s = 0.0f;
            for (int c = 0; c < D_OUT; c++)
                s = fmaf(W[c * D_IN + k], watt[c], s);
            g_u[k] = s;
        }
    } else {
        int idx = (blockIdx.x - EB - 1) * 256 + threadIdx.x;   // 0..12287
        int c = idx & 63;
        int k = idx >> 6;
        g_wt[k * 64 + c] = W[c * 192 + k];
    }
}

// ---------------- kernel 2: SINGLE-PASS fused logits+softmax+aggregation ---
// Measured 115us @ 73% DRAM (X read once). Unchanged.
__global__ __launch_bounds__(256) void aggregate_kernel(
    const float* __restrict__ X, int n_nodes)
{
    const int node = (blockIdx.x * blockDim.x + threadIdx.x) >> 5;
    if (node >= n_nodes) return;
    const int lane = threadIdx.x & 31;
    const int deg = min(g_cnt[node], CAP);

    const float2* u2 = (const float2*)g_u;
    const float2 ua = u2[lane];
    const float2 ub = u2[32 + lane];
    const float2 uc = u2[64 + lane];

    float2 a0 = make_float2(0.f, 0.f);
    float2 a1 = make_float2(0.f, 0.f);
    float2 a2 = make_float2(0.f, 0.f);
    float dsum = 0.0f;
    const float2* X2 = (const float2*)X;
    const int* bkt = g_bkt + (size_t)node * CAP;

    int base = 0;
    for (; base + 4 <= deg; base += 4) {
        int e0 = bkt[base], e1 = bkt[base + 1];
        int e2 = bkt[base + 2], e3 = bkt[base + 3];
        const float2* r0 = X2 + (size_t)e0 * 96;
        const float2* r1 = X2 + (size_t)e1 * 96;
        const float2* r2 = X2 + (size_t)e2 * 96;
        const float2* r3 = X2 + (size_t)e3 * 96;
        float2 v00 = r0[lane], v01 = r0[32 + lane], v02 = r0[64 + lane];
        float2 v10 = r1[lane], v11 = r1[32 + lane], v12 = r1[64 + lane];
        float2 v20 = r2[lane], v21 = r2[32 + lane], v22 = r2[64 + lane];
        float2 v30 = r3[lane], v31 = r3[32 + lane], v32 = r3[64 + lane];

        float d0 = fmaf(v00.x, ua.x, fmaf(v00.y, ua.y,
                   fmaf(v01.x, ub.x, fmaf(v01.y, ub.y,
                   fmaf(v02.x, uc.x, v02.y * uc.y)))));
        float d1 = fmaf(v10.x, ua.x, fmaf(v10.y, ua.y,
                   fmaf(v11.x, ub.x, fmaf(v11.y, ub.y,
                   fmaf(v12.x, uc.x, v12.y * uc.y)))));
        float d2 = fmaf(v20.x, ua.x, fmaf(v20.y, ua.y,
                   fmaf(v21.x, ub.x, fmaf(v21.y, ub.y,
                   fmaf(v22.x, uc.x, v22.y * uc.y)))));
        float d3 = fmaf(v30.x, ua.x, fmaf(v30.y, ua.y,
                   fmaf(v31.x, ub.x, fmaf(v31.y, ub.y,
                   fmaf(v32.x, uc.x, v32.y * uc.y)))));
#pragma unroll
        for (int m = 16; m >= 1; m >>= 1) {
            d0 += __shfl_xor_sync(0xffffffffu, d0, m);
            d1 += __shfl_xor_sync(0xffffffffu, d1, m);
            d2 += __shfl_xor_sync(0xffffffffu, d2, m);
            d3 += __shfl_xor_sync(0xffffffffu, d3, m);
        }
        float w0 = expf(mish(d0));
        float w1 = expf(mish(d1));
        float w2 = expf(mish(d2));
        float w3 = expf(mish(d3));
        dsum += (w0 + w1) + (w2 + w3);
        a0.x = fmaf(v00.x, w0, a0.x); a0.y = fmaf(v00.y, w0, a0.y);
        a1.x = fmaf(v01.x, w0, a1.x); a1.y = fmaf(v01.y, w0, a1.y);
        a2.x = fmaf(v02.x, w0, a2.x); a2.y = fmaf(v02.y, w0, a2.y);
        a0.x = fmaf(v10.x, w1, a0.x); a0.y = fmaf(v10.y, w1, a0.y);
        a1.x = fmaf(v11.x, w1, a1.x); a1.y = fmaf(v11.y, w1, a1.y);
        a2.x = fmaf(v12.x, w1, a2.x); a2.y = fmaf(v12.y, w1, a2.y);
        a0.x = fmaf(v20.x, w2, a0.x); a0.y = fmaf(v20.y, w2, a0.y);
        a1.x = fmaf(v21.x, w2, a1.x); a1.y = fmaf(v21.y, w2, a1.y);
        a2.x = fmaf(v22.x, w2, a2.x); a2.y = fmaf(v22.y, w2, a2.y);
        a0.x = fmaf(v30.x, w3, a0.x); a0.y = fmaf(v30.y, w3, a0.y);
        a1.x = fmaf(v31.x, w3, a1.x); a1.y = fmaf(v31.y, w3, a1.y);
        a2.x = fmaf(v32.x, w3, a2.x); a2.y = fmaf(v32.y, w3, a2.y);
    }
    for (; base < deg; base++) {
        int e = bkt[base];
        const float2* r = X2 + (size_t)e * 96;
        float2 v0 = r[lane], v1 = r[32 + lane], v2 = r[64 + lane];
        float d = fmaf(v0.x, ua.x, fmaf(v0.y, ua.y,
                  fmaf(v1.x, ub.x, fmaf(v1.y, ub.y,
                  fmaf(v2.x, uc.x, v2.y * uc.y)))));
#pragma unroll
        for (int m = 16; m >= 1; m >>= 1)
            d += __shfl_xor_sync(0xffffffffu, d, m);
        float w = expf(mish(d));
        dsum += w;
        a0.x = fmaf(v0.x, w, a0.x); a0.y = fmaf(v0.y, w, a0.y);
        a1.x = fmaf(v1.x, w, a1.x); a1.y = fmaf(v1.y, w, a1.y);
        a2.x = fmaf(v2.x, w, a2.x); a2.y = fmaf(v2.y, w, a2.y);
    }

    const float inv = (deg > 0) ? (1.0f / dsum) : 0.0f;
    a0.x *= inv; a0.y *= inv;
    a1.x *= inv; a1.y *= inv;
    a2.x *= inv; a2.y *= inv;
    float2* dst = (float2*)&g_xagg[(size_t)node * D_IN];
    dst[lane] = a0;
    dst[32 + lane] = a1;
    dst[64 + lane] = a2;

    // restore zero-invariant for next call
    if (lane == 0) g_cnt[node] = 0;
}

// ---------------- kernel 3 (PROFILED): out = xagg @ W^T, v7 ----------------
// 128-node x 64-col tile, 256 threads, thread = 8 nodes x 4 cols.
// Per k4: 4 wv LDS.128 (reused by 8 nodes) + 8 xv LDS.128 = 12 LDS / 128 FMA.
// W fill cost halved per node vs v6. smem 146KB -> 1 CTA/SM (kernel proven
// occupancy-insensitive in R12/R13).
#define XSP 196
__global__ __launch_bounds__(256) void out_gemm_kernel(
    float* __restrict__ out, int n_nodes)
{
    extern __shared__ float smem[];
    float* wsm = smem;              // [192][64]  wsm[k*64+c]
    float* xs = smem + 192 * 64;    // [128][XSP]

    const int tid = threadIdx.x;
    // coalesced, conflict-free W fill (12288 floats = 3072 float4)
    const float4* wt4 = (const float4*)g_wt;
    float4* wsm4 = (float4*)wsm;
    for (int l = tid; l < 3072; l += 256)
        wsm4[l] = wt4[l];

    const int n0 = blockIdx.x * 128;
    for (int l = tid; l < 128 * 48; l += 256) {
        int n = l / 48, k4 = l % 48;
        float4 v = (n0 + n < n_nodes)
            ? *(const float4*)&g_xagg[(size_t)(n0 + n) * 192 + k4 * 4]
            : make_float4(0.f, 0.f, 0.f, 0.f);
        *(float4*)&xs[n * XSP + k4 * 4] = v;
    }
    __syncthreads();

    const int tx = tid & 15;        // col group: cols tx*4 .. +3
    const int ty = tid >> 4;        // node group: nodes ty*8 .. +7
    float acc[8][4];
#pragma unroll
    for (int i = 0; i < 8; i++)
#pragma unroll
        for (int j = 0; j < 4; j++) acc[i][j] = 0.0f;

    const float* xbase = &xs[ty * 8 * XSP];
    for (int k4 = 0; k4 < 48; k4++) {
        float4 wv[4];
#pragma unroll
        for (int kk = 0; kk < 4; kk++)
            wv[kk] = *(const float4*)&wsm[(k4 * 4 + kk) * 64 + tx * 4];
#pragma unroll
        for (int i = 0; i < 8; i++) {
            float4 xv = *(const float4*)&xbase[i * XSP + k4 * 4];
            acc[i][0] = fmaf(xv.x, wv[0].x, acc[i][0]);
            acc[i][1] = fmaf(xv.x, wv[0].y, acc[i][1]);
            acc[i][2] = fmaf(xv.x, wv[0].z, acc[i][2]);
            acc[i][3] = fmaf(xv.x, wv[0].w, acc[i][3]);
            acc[i][0] = fmaf(xv.y, wv[1].x, acc[i][0]);
            acc[i][1] = fmaf(xv.y, wv[1].y, acc[i][1]);
            acc[i][2] = fmaf(xv.y, wv[1].z, acc[i][2]);
            acc[i][3] = fmaf(xv.y, wv[1].w, acc[i][3]);
            acc[i][0] = fmaf(xv.z, wv[2].x, acc[i][0]);
            acc[i][1] = fmaf(xv.z, wv[2].y, acc[i][1]);
            acc[i][2] = fmaf(xv.z, wv[2].z, acc[i][2]);
            acc[i][3] = fmaf(xv.z, wv[2].w, acc[i][3]);
            acc[i][0] = fmaf(xv.w, wv[3].x, acc[i][0]);
            acc[i][1] = fmaf(xv.w, wv[3].y, acc[i][1]);
            acc[i][2] = fmaf(xv.w, wv[3].z, acc[i][2]);
            acc[i][3] = fmaf(xv.w, wv[3].w, acc[i][3]);
        }
    }
#pragma unroll
    for (int i = 0; i < 8; i++) {
        int n = n0 + ty * 8 + i;
        if (n < n_nodes)
            *(float4*)&out[(size_t)n * 64 + tx * 4] =
                make_float4(acc[i][0], acc[i][1], acc[i][2], acc[i][3]);
    }
}

// ---------------- launch -----------------------------------------------------
extern "C" void kernel_launch(void* const* d_in, const int* in_sizes, int n_in,
                              void* d_out, int out_size) {
    const float* X = (const float*)d_in[0];
    const int* idx32 = (const int*)d_in[1];
    const float* W = (const float*)d_in[2];
    const float* watt = (const float*)d_in[3];
    float* out = (float*)d_out;

    const int n_edges = in_sizes[0] / D_IN;   // 800000
    const int n_nodes = out_size / D_OUT;     // 50000

    const int outg_smem = (192 * 64 + 128 * XSP) * (int)sizeof(float); // 149504
    cudaFuncSetAttribute(out_gemm_kernel,
                         cudaFuncAttributeMaxDynamicSharedMemorySize, outg_smem);

    histfill_kernel<<<EB + 1 + 48, 256>>>(idx32, W, watt, n_edges);     // 1
    aggregate_kernel<<<(n_nodes * 32 + 255) / 256, 256>>>(X, n_nodes);  // 2
    out_gemm_kernel<<<(n_nodes + 127) / 128, 256, outg_smem>>>(out, n_nodes); // 3
}